// round 6
// baseline (speedup 1.0000x reference)
#include <cuda_runtime.h>
#include <math.h>

#define B 64
#define C 512
#define HW 1024
#define R 32
#define NTILE 8        // HW / 128
#define NSLOT 8        // one pooled partial per tile

typedef unsigned long long ull;

// packed f32x2 helpers (Blackwell sm_100a+)
#define PACKDUP(d, v) \
    asm("mov.b64 %0, {%1, %1};" : "=l"(d) : "r"(__float_as_uint(v)))
#define FMA2(d, a, b) \
    asm("fma.rn.f32x2 %0, %1, %2, %0;" : "+l"(d) : "l"(a), "l"(b))
#define UNPK2(lo, hi, p) \
    asm("mov.b64 {%0, %1}, %2;" : "=r"(lo), "=r"(hi) : "l"(p))

// ---------------- scratch (device globals: no allocation allowed) -------------
__device__ float g_feat[B * R * HW];        // 8 MB   feat_raw = w_eig @ x (no bias)
__device__ float g_poolpart[B * NSLOT * C]; // 1 MB   partial sums for pooled
__device__ float g_covpart[B * 4 * R * R];  // 1 MB   raw Gram partials
__device__ float g_sp[B * HW];              // 256 KB spatial logits (no bias)
__device__ float g_ca[B * C];               // 128 KB channel attention
__device__ float g_att[B * HW];             // 256 KB eigen_att * spatial_att

// ============================================================================
// Pass 1: barrier-free register GEMM, 256 threads / 8 warps per CTA.
// CTA = (b, 128-n tile). Warp w owns rows 4w..4w+3; thread owns 4 n
// (ncol = lane*4) -> 8 packed f32x2 accumulators (16 regs, no spills).
// Per channel: 1 coalesced LDG.128 (reg double buffer, groups of 4 ch)
// + 1 broadcast LDS.128 (weights) + 4 movs + 8 FFMA2. No per-chunk
// __syncthreads (only around the w_eig half reload at c=256).
// Duty (spatial FMA + pooled shfl-reduce for channel c) -> warp c&7:
// perfectly balanced, 1 shfl chain per warp per 8 channels.
// ============================================================================
__global__ __launch_bounds__(256, 3) void pass1(const float* __restrict__ x,
                                                const float* __restrict__ w_eig,
                                                const float* __restrict__ w_sp) {
    __shared__ __align__(16) float we_s[256][36];   // 36 KB, rows 144B
    __shared__ float wsp_s[512];
    __shared__ float spool[512];
    __shared__ float sps[8][128];

    int b = blockIdx.x >> 3;
    int tile = blockIdx.x & 7;
    int n0 = tile << 7;
    int tid = threadIdx.x, lane = tid & 31, warp = tid >> 5;
    int r0 = warp << 2;          // 4 r rows per warp (8 warps cover 32)
    int ncol = lane << 2;        // 4 n cols per thread

    // stage w_eig half 0 (channels 0..255), transposed to [cc][r]
    for (int idx = tid; idx < 256 * 32; idx += 256) {
        int rr = idx >> 8;
        int cc = idx & 255;
        we_s[cc][rr] = w_eig[rr * C + cc];
    }
    for (int idx = tid; idx < 512; idx += 256) wsp_s[idx] = w_sp[idx];

    const float* xp = x + ((size_t)b * C) * HW + n0 + ncol;

    ull acc[8];   // [rpair 0..1][n 0..3]
#pragma unroll
    for (int i = 0; i < 8; i++) acc[i] = 0ull;
    float sp4[4] = {0.f, 0.f, 0.f, 0.f};

    float4 bufA[4], bufB[4];
#pragma unroll
    for (int k = 0; k < 4; k++) bufA[k] = *(const float4*)(xp + (size_t)k * HW);

    __syncthreads();

#define GRP_COMPUTE(BUF, C0)                                                   \
    {                                                                          \
        _Pragma("unroll")                                                      \
        for (int k = 0; k < 4; k++) {                                          \
            int c = (C0) + k;                                                  \
            int cl = c & 255;                                                  \
            float4 xv = BUF[k];                                                \
            if ((c & 7) == warp) {                                             \
                float wv = wsp_s[c];                                           \
                sp4[0] = fmaf(wv, xv.x, sp4[0]);                               \
                sp4[1] = fmaf(wv, xv.y, sp4[1]);                               \
                sp4[2] = fmaf(wv, xv.z, sp4[2]);                               \
                sp4[3] = fmaf(wv, xv.w, sp4[3]);                               \
                float t = (xv.x + xv.y) + (xv.z + xv.w);                       \
                t += __shfl_xor_sync(0xffffffffu, t, 16);                      \
                t += __shfl_xor_sync(0xffffffffu, t, 8);                       \
                t += __shfl_xor_sync(0xffffffffu, t, 4);                       \
                t += __shfl_xor_sync(0xffffffffu, t, 2);                       \
                t += __shfl_xor_sync(0xffffffffu, t, 1);                       \
                if (lane == 0) spool[c] = t;                                   \
            }                                                                  \
            ull xp0, xp1, xp2, xp3;                                            \
            PACKDUP(xp0, xv.x);                                                \
            PACKDUP(xp1, xv.y);                                                \
            PACKDUP(xp2, xv.z);                                                \
            PACKDUP(xp3, xv.w);                                                \
            ulonglong2 wa = *(const ulonglong2*)&we_s[cl][r0];                 \
            FMA2(acc[0], wa.x, xp0);                                           \
            FMA2(acc[1], wa.x, xp1);                                           \
            FMA2(acc[2], wa.x, xp2);                                           \
            FMA2(acc[3], wa.x, xp3);                                           \
            FMA2(acc[4], wa.y, xp0);                                           \
            FMA2(acc[5], wa.y, xp1);                                           \
            FMA2(acc[6], wa.y, xp2);                                           \
            FMA2(acc[7], wa.y, xp3);                                           \
        }                                                                      \
    }

    for (int gg = 0; gg < 128; gg += 2) {
        if (gg == 64) {
            // resync; reload we_s with channels 256..511
            __syncthreads();
            for (int idx = tid; idx < 256 * 32; idx += 256) {
                int rr = idx >> 8;
                int cc = idx & 255;
                we_s[cc][rr] = w_eig[rr * C + 256 + cc];
            }
            __syncthreads();
        }
        int c0 = gg << 2;
        // prefetch group gg+1 into bufB, compute group gg from bufA
#pragma unroll
        for (int k = 0; k < 4; k++)
            bufB[k] = *(const float4*)(xp + (size_t)(c0 + 4 + k) * HW);
        GRP_COMPUTE(bufA, c0)
        // prefetch group gg+2 into bufA (unless done), compute gg+1 from bufB
        if (gg < 126) {
#pragma unroll
            for (int k = 0; k < 4; k++)
                bufA[k] = *(const float4*)(xp + (size_t)(c0 + 8 + k) * HW);
        }
        GRP_COMPUTE(bufB, c0 + 4)
    }
#undef GRP_COMPUTE

    // unpack r-pairs and store feat (coalesced STG.128)
#pragma unroll
    for (int rp = 0; rp < 2; rp++) {
        float lo[4], hi[4];
#pragma unroll
        for (int n = 0; n < 4; n++) {
            unsigned int l, h;
            UNPK2(l, h, acc[rp * 4 + n]);
            lo[n] = __uint_as_float(l);
            hi[n] = __uint_as_float(h);
        }
        *(float4*)&g_feat[((size_t)(b * R + r0 + 2 * rp)) * HW + n0 + ncol] =
            make_float4(lo[0], lo[1], lo[2], lo[3]);
        *(float4*)&g_feat[((size_t)(b * R + r0 + 2 * rp + 1)) * HW + n0 + ncol] =
            make_float4(hi[0], hi[1], hi[2], hi[3]);
    }

    // combine per-warp spatial partials (each warp covered channels c&7==warp)
    *(float4*)&sps[warp][ncol] = make_float4(sp4[0], sp4[1], sp4[2], sp4[3]);
    __syncthreads();
    if (tid < 128) {
        float s = 0.f;
#pragma unroll
        for (int w = 0; w < 8; w++) s += sps[w][tid];
        g_sp[(size_t)b * HW + n0 + tid] = s;
    }
    for (int idx = tid; idx < C; idx += 256)
        g_poolpart[((size_t)(b * NSLOT) + tile) * C + idx] = spool[idx];
}

// ============================================================================
// Pass 2a: raw Gram partials. CTA = (b, n-quarter of 256), 256 threads.
// ============================================================================
__global__ __launch_bounds__(256) void pass2a() {
    __shared__ __align__(16) float fcT[256][36];
    int b = blockIdx.x >> 2;
    int q = blockIdx.x & 3;
    int tid = threadIdx.x;

    for (int idx = tid; idx < R * 256; idx += 256) {
        int r = idx >> 8, n = idx & 255;
        fcT[n][r] = g_feat[((size_t)(b * R + r)) * HW + q * 256 + n];
    }
    __syncthreads();

    int my_r = tid >> 3;
    int s0 = (tid & 7) << 2;
    float g4[4] = {0.f, 0.f, 0.f, 0.f};
#pragma unroll 8
    for (int n = 0; n < 256; n++) {
        float fr = fcT[n][my_r];
        float4 fs = *(const float4*)&fcT[n][s0];
        g4[0] = fmaf(fr, fs.x, g4[0]);
        g4[1] = fmaf(fr, fs.y, g4[1]);
        g4[2] = fmaf(fr, fs.z, g4[2]);
        g4[3] = fmaf(fr, fs.w, g4[3]);
    }
    *(float4*)&g_covpart[((size_t)(b * 4 + q)) * (R * R) + my_r * R + s0] =
        make_float4(g4[0], g4[1], g4[2], g4[3]);
}

// ============================================================================
// Pass 2b: per-batch finish. pooled -> MLP (g_ca) + mu; cov assembly;
// power iteration; att projection + min/max + sigmoids.
// ============================================================================
__global__ __launch_bounds__(256) void pass2b(const float* __restrict__ w_fc1,
                                              const float* __restrict__ b_fc1,
                                              const float* __restrict__ w_fc2,
                                              const float* __restrict__ b_fc2,
                                              const float* __restrict__ w_eig,
                                              const float* __restrict__ b_sp,
                                              const float* __restrict__ v0) {
    __shared__ float s_pool[C];
    __shared__ float s_mu[R];
    __shared__ float s_ca1[R];
    __shared__ float s_cov[R * R];
    __shared__ float s_v[R];
    __shared__ float s_redmin[8], s_redmax[8];
    __shared__ float s_c0, s_amin, s_amax;

    int b = blockIdx.x;
    int tid = threadIdx.x, lane = tid & 31, warp = tid >> 5;

    // 1. pooled = sum of 8 tile partials / HW
    for (int c = tid; c < C; c += 256) {
        float s = 0.f;
#pragma unroll
        for (int k = 0; k < NSLOT; k++) s += g_poolpart[((size_t)b * NSLOT + k) * C + c];
        s_pool[c] = s * (1.0f / HW);
    }
    __syncthreads();

    // 2. ca1 = relu(pooled @ w_fc1^T + b_fc1); mu = w_eig @ pooled
    for (int k = 0; k < 4; k++) {
        int r = warp + k * 8;
        float s1 = 0.f, s2 = 0.f;
        for (int c = lane; c < C; c += 32) {
            float p = s_pool[c];
            s1 = fmaf(p, w_fc1[r * C + c], s1);
            s2 = fmaf(p, w_eig[r * C + c], s2);
        }
        for (int o = 16; o > 0; o >>= 1) {
            s1 += __shfl_xor_sync(0xffffffffu, s1, o);
            s2 += __shfl_xor_sync(0xffffffffu, s2, o);
        }
        if (lane == 0) {
            s_ca1[r] = fmaxf(s1 + b_fc1[r], 0.f);
            s_mu[r] = s2;
        }
    }
    __syncthreads();

    // 3. channel attention: sigmoid(ca1 @ w_fc2^T + b_fc2)
    for (int c = tid; c < C; c += 256) {
        float a = b_fc2[c];
#pragma unroll
        for (int r = 0; r < R; r++) a = fmaf(s_ca1[r], w_fc2[c * R + r], a);
        g_ca[(size_t)b * C + c] = 1.f / (1.f + expf(-a));
    }

    // 4. cov = (sum_q G_q - HW*mu*mu^T)/(HW-1) + 1e-5 I
    for (int e0 = tid * 4; e0 < R * R; e0 += 256 * 4) {
#pragma unroll
        for (int i = 0; i < 4; i++) {
            int e = e0 + i;
            int r = e >> 5, s = e & 31;
            float g = 0.f;
#pragma unroll
            for (int q = 0; q < 4; q++)
                g += g_covpart[((size_t)(b * 4 + q)) * (R * R) + e];
            float v = (g - (float)HW * s_mu[r] * s_mu[s]) * (1.0f / (HW - 1));
            if (r == s) v += 1e-5f;
            s_cov[e] = v;
        }
    }
    __syncthreads();

    // 5. power iteration (warp 0)
    if (warp == 0) {
        float v = v0[b * R + lane];
        float nr = v * v;
        for (int o = 16; o > 0; o >>= 1) nr += __shfl_xor_sync(0xffffffffu, nr, o);
        v = v / sqrtf(nr);
        for (int it = 0; it < 5; it++) {
            float nv = 0.f;
#pragma unroll
            for (int s = 0; s < R; s++)
                nv = fmaf(s_cov[s * R + lane], __shfl_sync(0xffffffffu, v, s), nv);
            float nn = nv * nv;
            for (int o = 16; o > 0; o >>= 1) nn += __shfl_xor_sync(0xffffffffu, nn, o);
            v = nv / (sqrtf(nn) + 1e-10f);
        }
        s_v[lane] = v;
        float c0 = v * s_mu[lane];
        for (int o = 16; o > 0; o >>= 1) c0 += __shfl_xor_sync(0xffffffffu, c0, o);
        if (lane == 0) s_c0 = c0;
    }
    __syncthreads();

    // 6. att[n] = v . feat_raw[:,n] - c0 ; min/max; sigmoids
    float attv[4];
#pragma unroll
    for (int k = 0; k < 4; k++) {
        int n = k * 256 + tid;
        float a = 0.f;
#pragma unroll
        for (int r = 0; r < R; r++)
            a = fmaf(s_v[r], g_feat[((size_t)(b * R + r)) * HW + n], a);
        attv[k] = a - s_c0;
    }
    float mn = attv[0], mx = attv[0];
#pragma unroll
    for (int k = 1; k < 4; k++) { mn = fminf(mn, attv[k]); mx = fmaxf(mx, attv[k]); }
    for (int o = 16; o > 0; o >>= 1) {
        mn = fminf(mn, __shfl_xor_sync(0xffffffffu, mn, o));
        mx = fmaxf(mx, __shfl_xor_sync(0xffffffffu, mx, o));
    }
    if (lane == 0) { s_redmin[warp] = mn; s_redmax[warp] = mx; }
    __syncthreads();
    if (tid == 0) {
        float a = s_redmin[0], m = s_redmax[0];
        for (int w = 1; w < 8; w++) { a = fminf(a, s_redmin[w]); m = fmaxf(m, s_redmax[w]); }
        s_amin = a; s_amax = m;
    }
    __syncthreads();
    float amin = s_amin;
    float denom = (s_amax - amin) + 1e-10f;
    float bspv = b_sp[0];
#pragma unroll
    for (int k = 0; k < 4; k++) {
        int n = k * 256 + tid;
        float e = 1.f / (1.f + expf(-((attv[k] - amin) / denom)));
        float sl = g_sp[(size_t)b * HW + n] + bspv;
        float sa = 1.f / (1.f + expf(-sl));
        g_att[(size_t)b * HW + n] = e * sa;
    }
}

// ============================================================================
// Pass 3: out = x * (1 + ca[b,c] * att[b,n])  (2x float4 per thread)
// ============================================================================
__global__ __launch_bounds__(256) void pass3(const float* __restrict__ x,
                                             float* __restrict__ out) {
    unsigned int base = blockIdx.x * 512u + threadIdx.x;
#pragma unroll
    for (int u = 0; u < 2; u++) {
        unsigned int i = base + u * 256u;      // float4 index
        int n4 = i & 255;                      // HW/4 = 256
        int c = (i >> 8) & (C - 1);
        int b = i >> 17;
        float ca = g_ca[b * C + c];
        float4 at = ((const float4*)g_att)[(size_t)b * (HW / 4) + n4];
        float4 xv = ((const float4*)x)[i];
        float4 o;
        o.x = fmaf(xv.x, ca * at.x, xv.x);
        o.y = fmaf(xv.y, ca * at.y, xv.y);
        o.z = fmaf(xv.z, ca * at.z, xv.z);
        o.w = fmaf(xv.w, ca * at.w, xv.w);
        ((float4*)out)[i] = o;
    }
}

extern "C" void kernel_launch(void* const* d_in, const int* in_sizes, int n_in,
                              void* d_out, int out_size) {
    const float* x     = (const float*)d_in[0];
    const float* w_fc1 = (const float*)d_in[1];
    const float* b_fc1 = (const float*)d_in[2];
    const float* w_fc2 = (const float*)d_in[3];
    const float* b_fc2 = (const float*)d_in[4];
    const float* w_eig = (const float*)d_in[5];
    /* d_in[6] = b_eig: cancels in feat_c and in mu -> unused */
    const float* w_sp  = (const float*)d_in[7];
    const float* b_sp  = (const float*)d_in[8];
    const float* v0    = (const float*)d_in[9];
    float* out = (float*)d_out;

    pass1<<<B * NTILE, 256>>>(x, w_eig, w_sp);
    pass2a<<<B * 4, 256>>>();
    pass2b<<<B, 256>>>(w_fc1, b_fc1, w_fc2, b_fc2, w_eig, b_sp, v0);
    pass3<<<(B * C * HW / 4) / 512, 256>>>(x, out);
}

// round 8
// speedup vs baseline: 1.5207x; 1.5207x over previous
#include <cuda_runtime.h>
#include <math.h>

#define B 64
#define C 512
#define HW 1024
#define R 32
#define T1 128
#define NTILE 8        // HW / 128
#define NSLOT 8        // one pooled partial per tile

typedef unsigned long long ull;

// packed f32x2 helpers (Blackwell sm_100a+)
#define PACKDUP(d, v) \
    asm("mov.b64 %0, {%1, %1};" : "=l"(d) : "r"(__float_as_uint(v)))
#define FMA2(d, a, b) \
    asm("fma.rn.f32x2 %0, %1, %2, %0;" : "+l"(d) : "l"(a), "l"(b))
#define UNPK2(lo, hi, p) \
    asm("mov.b64 {%0, %1}, %2;" : "=r"(lo), "=r"(hi) : "l"(p))

// cp.async helpers (Ampere+)
#define CP_ASYNC16(dst_u32, src_ptr) \
    asm volatile("cp.async.cg.shared.global [%0], [%1], 16;" \
                 :: "r"(dst_u32), "l"(src_ptr))
#define CP_COMMIT() asm volatile("cp.async.commit_group;" ::: "memory")
#define CP_WAIT2()  asm volatile("cp.async.wait_group 2;" ::: "memory")

// ---------------- scratch (device globals: no allocation allowed) -------------
__device__ float g_feat[B * R * HW];        // 8 MB   feat_raw = w_eig @ x (no bias)
__device__ float g_poolpart[B * NSLOT * C]; // 1 MB   partial sums for pooled
__device__ float g_covpart[B * 4 * R * R];  // 1 MB   raw Gram partials
__device__ float g_sp[B * HW];              // 256 KB spatial logits (no bias)
__device__ float g_ca[B * C];               // 128 KB channel attention
__device__ float g_att[B * HW];             // 256 KB eigen_att * spatial_att

// ============================================================================
// Pass 1: smem-staged register GEMM with cp.async pipeline (40 KB smem).
// CTA = (b, 128-n tile), 128 threads / 4 warps. Thread tile 8r x 4n held as
// 16 packed f32x2 accumulators. x flows GMEM -> SMEM via cp.async.cg (16B),
// 4 pipeline stages of 8 channels each; 3 chunks in flight while computing
// -> DRAM latency hidden. One __syncthreads per chunk.
// Weight window = 128 channels (18 KB), reloaded at chunks 16/32/48.
// Per channel per thread: 1 x-LDS.128 + 2 broadcast w-LDS.128 + 4 mov
// + 16 FFMA2. Duty (spatial FMA + pooled shfl chain for channel c): warp c&3.
// ============================================================================
__global__ __launch_bounds__(T1, 4) void pass1(const float* __restrict__ x,
                                               const float* __restrict__ w_eig,
                                               const float* __restrict__ w_sp) {
    __shared__ __align__(16) float we_s[128][36];   // 18 KB window
    __shared__ __align__(16) float xs[4][8][128];   // 16 KB, 4 stages
    __shared__ float wsp_s[512];
    __shared__ float spool[512];
    __shared__ float sps[4][128];

    int b = blockIdx.x >> 3;
    int tile = blockIdx.x & 7;
    int n0 = tile << 7;
    int tid = threadIdx.x, lane = tid & 31, warp = tid >> 5;
    int r0 = warp << 3;          // 8 r rows per warp
    int ncol = lane << 2;        // 4 n cols per thread

    // stage weight window 0 (channels 0..127), transposed to [cc][r]
    for (int idx = tid; idx < 128 * 32; idx += T1) {
        int rr = idx >> 7;
        int cc = idx & 127;
        we_s[cc][rr] = w_eig[rr * C + cc];
    }
    for (int idx = tid; idx < 512; idx += T1) wsp_s[idx] = w_sp[idx];

    const float* xg = x + ((size_t)b * C) * HW + n0;
    unsigned int xs_base = (unsigned int)__cvta_generic_to_shared(&xs[0][0][0]);

    // per-thread copy slots: 2 x 16B per chunk (8 ch x 128 n x 4B = 4 KB)
    int cl0 = tid >> 5;              // j=0: channels 0..3 of chunk
    int ns0 = (tid & 31) << 2;       //      float offset of 16B segment
    int cl1 = 4 + (tid >> 5);        // j=1: channels 4..7

#define ISSUE_CHUNK(CC)                                                        \
    {                                                                          \
        int st_ = (CC) & 3;                                                    \
        const float* s0_ = xg + (size_t)((CC) * 8 + cl0) * HW + ns0;           \
        const float* s1_ = xg + (size_t)((CC) * 8 + cl1) * HW + ns0;           \
        unsigned int d0_ = xs_base + (((st_ * 8 + cl0) << 7) + ns0) * 4u;      \
        unsigned int d1_ = xs_base + (((st_ * 8 + cl1) << 7) + ns0) * 4u;      \
        CP_ASYNC16(d0_, s0_);                                                  \
        CP_ASYNC16(d1_, s1_);                                                  \
    }

    // prologue: 3 chunks in flight
    ISSUE_CHUNK(0) CP_COMMIT();
    ISSUE_CHUNK(1) CP_COMMIT();
    ISSUE_CHUNK(2) CP_COMMIT();

    ull acc[16];   // [rpair 0..3][n 0..3]
#pragma unroll
    for (int i = 0; i < 16; i++) acc[i] = 0ull;
    float sp4[4] = {0.f, 0.f, 0.f, 0.f};

    __syncthreads();   // we_s/wsp_s staged

    for (int chunk = 0; chunk < 64; chunk++) {
        if (chunk > 0 && (chunk & 15) == 0) {
            // all warps done reading the previous weight window
            __syncthreads();
            int cbase = chunk << 3;   // window start channel
            for (int idx = tid; idx < 128 * 32; idx += T1) {
                int rr = idx >> 7;
                int cc = idx & 127;
                we_s[cc][rr] = w_eig[rr * C + cbase + cc];
            }
            // visibility covered by the per-chunk barrier below
        }
        CP_WAIT2();          // this chunk's copy group complete
        __syncthreads();     // all threads' copies + weight reload visible

        int st = chunk & 3;
        int c0 = chunk << 3;
#pragma unroll
        for (int k = 0; k < 8; k++) {
            int c = c0 + k;
            int cl = c & 127;
            float4 xv = *(const float4*)&xs[st][k][ncol];
            if ((c & 3) == warp) {
                float wv = wsp_s[c];
                sp4[0] = fmaf(wv, xv.x, sp4[0]);
                sp4[1] = fmaf(wv, xv.y, sp4[1]);
                sp4[2] = fmaf(wv, xv.z, sp4[2]);
                sp4[3] = fmaf(wv, xv.w, sp4[3]);
                float t = (xv.x + xv.y) + (xv.z + xv.w);
                t += __shfl_xor_sync(0xffffffffu, t, 16);
                t += __shfl_xor_sync(0xffffffffu, t, 8);
                t += __shfl_xor_sync(0xffffffffu, t, 4);
                t += __shfl_xor_sync(0xffffffffu, t, 2);
                t += __shfl_xor_sync(0xffffffffu, t, 1);
                if (lane == 0) spool[c] = t;
            }
            ull xp0, xp1, xp2, xp3;
            PACKDUP(xp0, xv.x);
            PACKDUP(xp1, xv.y);
            PACKDUP(xp2, xv.z);
            PACKDUP(xp3, xv.w);
            const ulonglong2* wrow = (const ulonglong2*)&we_s[cl][r0];
            ulonglong2 wa = wrow[0];
            ulonglong2 wb = wrow[1];
            FMA2(acc[0],  wa.x, xp0);
            FMA2(acc[1],  wa.x, xp1);
            FMA2(acc[2],  wa.x, xp2);
            FMA2(acc[3],  wa.x, xp3);
            FMA2(acc[4],  wa.y, xp0);
            FMA2(acc[5],  wa.y, xp1);
            FMA2(acc[6],  wa.y, xp2);
            FMA2(acc[7],  wa.y, xp3);
            FMA2(acc[8],  wb.x, xp0);
            FMA2(acc[9],  wb.x, xp1);
            FMA2(acc[10], wb.x, xp2);
            FMA2(acc[11], wb.x, xp3);
            FMA2(acc[12], wb.y, xp0);
            FMA2(acc[13], wb.y, xp1);
            FMA2(acc[14], wb.y, xp2);
            FMA2(acc[15], wb.y, xp3);
        }

        // issue copies for chunk+3 (stage (chunk+3)&3 != stage being read)
        if (chunk < 61) ISSUE_CHUNK(chunk + 3)
        CP_COMMIT();   // commit (possibly empty) to keep group counts aligned
    }
#undef ISSUE_CHUNK

    // unpack r-pairs and store feat (coalesced STG.128)
#pragma unroll
    for (int rp = 0; rp < 4; rp++) {
        float lo[4], hi[4];
#pragma unroll
        for (int n = 0; n < 4; n++) {
            unsigned int l, h;
            UNPK2(l, h, acc[rp * 4 + n]);
            lo[n] = __uint_as_float(l);
            hi[n] = __uint_as_float(h);
        }
        *(float4*)&g_feat[((size_t)(b * R + r0 + 2 * rp)) * HW + n0 + ncol] =
            make_float4(lo[0], lo[1], lo[2], lo[3]);
        *(float4*)&g_feat[((size_t)(b * R + r0 + 2 * rp + 1)) * HW + n0 + ncol] =
            make_float4(hi[0], hi[1], hi[2], hi[3]);
    }

    // combine per-warp spatial partials (warp w covered channels c&3==w)
    *(float4*)&sps[warp][ncol] = make_float4(sp4[0], sp4[1], sp4[2], sp4[3]);
    __syncthreads();
    {
        float s = (sps[0][tid] + sps[1][tid]) + (sps[2][tid] + sps[3][tid]);
        g_sp[(size_t)b * HW + n0 + tid] = s;
    }
    for (int idx = tid; idx < C; idx += T1)
        g_poolpart[((size_t)(b * NSLOT) + tile) * C + idx] = spool[idx];
}

// ============================================================================
// Pass 2a: raw Gram partials. CTA = (b, n-quarter of 256), 256 threads.
// ============================================================================
__global__ __launch_bounds__(256) void pass2a() {
    __shared__ __align__(16) float fcT[256][36];
    int b = blockIdx.x >> 2;
    int q = blockIdx.x & 3;
    int tid = threadIdx.x;

    for (int idx = tid; idx < R * 256; idx += 256) {
        int r = idx >> 8, n = idx & 255;
        fcT[n][r] = g_feat[((size_t)(b * R + r)) * HW + q * 256 + n];
    }
    __syncthreads();

    int my_r = tid >> 3;
    int s0 = (tid & 7) << 2;
    float g4[4] = {0.f, 0.f, 0.f, 0.f};
#pragma unroll 8
    for (int n = 0; n < 256; n++) {
        float fr = fcT[n][my_r];
        float4 fs = *(const float4*)&fcT[n][s0];
        g4[0] = fmaf(fr, fs.x, g4[0]);
        g4[1] = fmaf(fr, fs.y, g4[1]);
        g4[2] = fmaf(fr, fs.z, g4[2]);
        g4[3] = fmaf(fr, fs.w, g4[3]);
    }
    *(float4*)&g_covpart[((size_t)(b * 4 + q)) * (R * R) + my_r * R + s0] =
        make_float4(g4[0], g4[1], g4[2], g4[3]);
}

// ============================================================================
// Pass 2b: per-batch finish. pooled -> MLP (g_ca) + mu; cov assembly;
// power iteration; att projection + min/max + sigmoids.
// ============================================================================
__global__ __launch_bounds__(256) void pass2b(const float* __restrict__ w_fc1,
                                              const float* __restrict__ b_fc1,
                                              const float* __restrict__ w_fc2,
                                              const float* __restrict__ b_fc2,
                                              const float* __restrict__ w_eig,
                                              const float* __restrict__ b_sp,
                                              const float* __restrict__ v0) {
    __shared__ float s_pool[C];
    __shared__ float s_mu[R];
    __shared__ float s_ca1[R];
    __shared__ float s_cov[R * R];
    __shared__ float s_v[R];
    __shared__ float s_redmin[8], s_redmax[8];
    __shared__ float s_c0, s_amin, s_amax;

    int b = blockIdx.x;
    int tid = threadIdx.x, lane = tid & 31, warp = tid >> 5;

    // 1. pooled = sum of 8 tile partials / HW
    for (int c = tid; c < C; c += 256) {
        float s = 0.f;
#pragma unroll
        for (int k = 0; k < NSLOT; k++) s += g_poolpart[((size_t)b * NSLOT + k) * C + c];
        s_pool[c] = s * (1.0f / HW);
    }
    __syncthreads();

    // 2. ca1 = relu(pooled @ w_fc1^T + b_fc1); mu = w_eig @ pooled
    for (int k = 0; k < 4; k++) {
        int r = warp + k * 8;
        float s1 = 0.f, s2 = 0.f;
        for (int c = lane; c < C; c += 32) {
            float p = s_pool[c];
            s1 = fmaf(p, w_fc1[r * C + c], s1);
            s2 = fmaf(p, w_eig[r * C + c], s2);
        }
        for (int o = 16; o > 0; o >>= 1) {
            s1 += __shfl_xor_sync(0xffffffffu, s1, o);
            s2 += __shfl_xor_sync(0xffffffffu, s2, o);
        }
        if (lane == 0) {
            s_ca1[r] = fmaxf(s1 + b_fc1[r], 0.f);
            s_mu[r] = s2;
        }
    }
    __syncthreads();

    // 3. channel attention: sigmoid(ca1 @ w_fc2^T + b_fc2)
    for (int c = tid; c < C; c += 256) {
        float a = b_fc2[c];
#pragma unroll
        for (int r = 0; r < R; r++) a = fmaf(s_ca1[r], w_fc2[c * R + r], a);
        g_ca[(size_t)b * C + c] = 1.f / (1.f + expf(-a));
    }

    // 4. cov = (sum_q G_q - HW*mu*mu^T)/(HW-1) + 1e-5 I
    for (int e0 = tid * 4; e0 < R * R; e0 += 256 * 4) {
#pragma unroll
        for (int i = 0; i < 4; i++) {
            int e = e0 + i;
            int r = e >> 5, s = e & 31;
            float g = 0.f;
#pragma unroll
            for (int q = 0; q < 4; q++)
                g += g_covpart[((size_t)(b * 4 + q)) * (R * R) + e];
            float v = (g - (float)HW * s_mu[r] * s_mu[s]) * (1.0f / (HW - 1));
            if (r == s) v += 1e-5f;
            s_cov[e] = v;
        }
    }
    __syncthreads();

    // 5. power iteration (warp 0)
    if (warp == 0) {
        float v = v0[b * R + lane];
        float nr = v * v;
        for (int o = 16; o > 0; o >>= 1) nr += __shfl_xor_sync(0xffffffffu, nr, o);
        v = v / sqrtf(nr);
        for (int it = 0; it < 5; it++) {
            float nv = 0.f;
#pragma unroll
            for (int s = 0; s < R; s++)
                nv = fmaf(s_cov[s * R + lane], __shfl_sync(0xffffffffu, v, s), nv);
            float nn = nv * nv;
            for (int o = 16; o > 0; o >>= 1) nn += __shfl_xor_sync(0xffffffffu, nn, o);
            v = nv / (sqrtf(nn) + 1e-10f);
        }
        s_v[lane] = v;
        float c0 = v * s_mu[lane];
        for (int o = 16; o > 0; o >>= 1) c0 += __shfl_xor_sync(0xffffffffu, c0, o);
        if (lane == 0) s_c0 = c0;
    }
    __syncthreads();

    // 6. att[n] = v . feat_raw[:,n] - c0 ; min/max; sigmoids
    float attv[4];
#pragma unroll
    for (int k = 0; k < 4; k++) {
        int n = k * 256 + tid;
        float a = 0.f;
#pragma unroll
        for (int r = 0; r < R; r++)
            a = fmaf(s_v[r], g_feat[((size_t)(b * R + r)) * HW + n], a);
        attv[k] = a - s_c0;
    }
    float mn = attv[0], mx = attv[0];
#pragma unroll
    for (int k = 1; k < 4; k++) { mn = fminf(mn, attv[k]); mx = fmaxf(mx, attv[k]); }
    for (int o = 16; o > 0; o >>= 1) {
        mn = fminf(mn, __shfl_xor_sync(0xffffffffu, mn, o));
        mx = fmaxf(mx, __shfl_xor_sync(0xffffffffu, mx, o));
    }
    if (lane == 0) { s_redmin[warp] = mn; s_redmax[warp] = mx; }
    __syncthreads();
    if (tid == 0) {
        float a = s_redmin[0], m = s_redmax[0];
        for (int w = 1; w < 8; w++) { a = fminf(a, s_redmin[w]); m = fmaxf(m, s_redmax[w]); }
        s_amin = a; s_amax = m;
    }
    __syncthreads();
    float amin = s_amin;
    float denom = (s_amax - amin) + 1e-10f;
    float bspv = b_sp[0];
#pragma unroll
    for (int k = 0; k < 4; k++) {
        int n = k * 256 + tid;
        float e = 1.f / (1.f + expf(-((attv[k] - amin) / denom)));
        float sl = g_sp[(size_t)b * HW + n] + bspv;
        float sa = 1.f / (1.f + expf(-sl));
        g_att[(size_t)b * HW + n] = e * sa;
    }
}

// ============================================================================
// Pass 3: out = x * (1 + ca[b,c] * att[b,n])  (2x float4 per thread)
// ============================================================================
__global__ __launch_bounds__(256) void pass3(const float* __restrict__ x,
                                             float* __restrict__ out) {
    unsigned int base = blockIdx.x * 512u + threadIdx.x;
#pragma unroll
    for (int u = 0; u < 2; u++) {
        unsigned int i = base + u * 256u;      // float4 index
        int n4 = i & 255;                      // HW/4 = 256
        int c = (i >> 8) & (C - 1);
        int b = i >> 17;
        float ca = g_ca[b * C + c];
        float4 at = ((const float4*)g_att)[(size_t)b * (HW / 4) + n4];
        float4 xv = ((const float4*)x)[i];
        float4 o;
        o.x = fmaf(xv.x, ca * at.x, xv.x);
        o.y = fmaf(xv.y, ca * at.y, xv.y);
        o.z = fmaf(xv.z, ca * at.z, xv.z);
        o.w = fmaf(xv.w, ca * at.w, xv.w);
        ((float4*)out)[i] = o;
    }
}

extern "C" void kernel_launch(void* const* d_in, const int* in_sizes, int n_in,
                              void* d_out, int out_size) {
    const float* x     = (const float*)d_in[0];
    const float* w_fc1 = (const float*)d_in[1];
    const float* b_fc1 = (const float*)d_in[2];
    const float* w_fc2 = (const float*)d_in[3];
    const float* b_fc2 = (const float*)d_in[4];
    const float* w_eig = (const float*)d_in[5];
    /* d_in[6] = b_eig: cancels in feat_c and in mu -> unused */
    const float* w_sp  = (const float*)d_in[7];
    const float* b_sp  = (const float*)d_in[8];
    const float* v0    = (const float*)d_in[9];
    float* out = (float*)d_out;

    pass1<<<B * NTILE, T1>>>(x, w_eig, w_sp);
    pass2a<<<B * 4, 256>>>();
    pass2b<<<B, 256>>>(w_fc1, b_fc1, w_fc2, b_fc2, w_eig, b_sp, v0);
    pass3<<<(B * C * HW / 4) / 512, 256>>>(x, out);
}